// round 3
// baseline (speedup 1.0000x reference)
#include <cuda_runtime.h>
#include <cuda_bf16.h>
#include <mma.h>

using namespace nvcuda;

// Problem constants (fixed shapes per reference setup_inputs)
#define N_NODES    100000
#define N_TYPES    7
#define E_PER_TYPE 250000
#define DIM        128

// Row-padded node count so the last GEMM tile can store unguarded.
// 782 tiles * 128 = 100096
#define N_PAD      100096

// Scratch:
//   g_y   : transformed features per type  [T, N_PAD, D]  (~359 MB)
//   g_cnt : per-(type,node) in-degree
//   g_inv : 1 / (T * max(cnt,1))  folded normalization
__device__ float g_y[(size_t)N_TYPES * N_PAD * DIM];
__device__ float g_cnt[N_TYPES * N_NODES];
__device__ float g_inv[N_TYPES * N_NODES];

// ---------------------------------------------------------------------------
// Kernel 1: zero the per-(type,node) counts (atomics accumulate across replays)
// ---------------------------------------------------------------------------
__global__ void zero_cnt_kernel() {
    const int total = N_TYPES * N_NODES;
    const int stride = gridDim.x * blockDim.x;
    for (int i = blockIdx.x * blockDim.x + threadIdx.x; i < total; i += stride)
        g_cnt[i] = 0.f;
}

// ---------------------------------------------------------------------------
// Kernel 2: count in-degree per (type, dst). One thread per edge.
// NOTE: edge_index is int32 (JAX x64-disabled downgrades jnp.int64 -> int32).
// Guards: out-of-range indices are skipped instead of faulting.
// ---------------------------------------------------------------------------
__global__ void cnt_kernel(const int* __restrict__ ei) {
    int idx = blockIdx.x * blockDim.x + threadIdx.x;
    if (idx >= N_TYPES * E_PER_TYPE) return;
    int t = idx / E_PER_TYPE;
    int e = idx - t * E_PER_TYPE;
    int dst = ei[(size_t)t * 2 * E_PER_TYPE + E_PER_TYPE + e];
    if ((unsigned)dst < (unsigned)N_NODES)
        atomicAdd(&g_cnt[t * N_NODES + dst], 1.0f);
}

// ---------------------------------------------------------------------------
// Kernel 3: initialize out with the bias term and build g_inv:
//   out[n,:] = (1/T) * sum_t (cnt[t,n] > 0) * b[t,:]
//   g_inv[t,n] = 1 / (T * max(cnt[t,n], 1))
// Thread = (node n, float4 index q in 0..31): cnt reads broadcast per warp
// group, out writes coalesced.
// ---------------------------------------------------------------------------
__global__ void init_out_kernel(const float* __restrict__ bg,
                                float4* __restrict__ out4) {
    int idx = blockIdx.x * blockDim.x + threadIdx.x;
    if (idx >= N_NODES * (DIM / 4)) return;
    int n = idx >> 5;          // node
    int q = idx & 31;          // which float4 of the 128-dim row

    float4 acc = make_float4(0.f, 0.f, 0.f, 0.f);
#pragma unroll
    for (int t = 0; t < N_TYPES; t++) {
        float c = g_cnt[t * N_NODES + n];
        if (q < N_TYPES && q == t)  // one lane per type writes inv
            g_inv[t * N_NODES + n] = 1.0f / ((float)N_TYPES * fmaxf(c, 1.0f));
        if (c > 0.f) {
            float4 bb = __ldg(((const float4*)bg) + t * (DIM / 4) + q);
            acc.x += bb.x; acc.y += bb.y; acc.z += bb.z; acc.w += bb.w;
        }
    }
    const float s = 1.0f / (float)N_TYPES;
    acc.x *= s; acc.y *= s; acc.z *= s; acc.w *= s;
    out4[(size_t)n * (DIM / 4) + q] = acc;
}

// ---------------------------------------------------------------------------
// Kernel 4: y[t] = x @ W[t]  via tf32 wmma (m16n16k8).
// Grid: (782 row tiles, 7 types). Block: 256 threads = 8 warps in a 2x4 grid;
// each warp owns a 64x32 output sub-tile (4x2 wmma tiles). BK = 32 staged in
// shared memory, tf32-converted on the smem write.
// ---------------------------------------------------------------------------
#define GA_LD 36   // 144 B rows: multiple of 16 B, bank-shifted
#define GB_LD 132

__global__ __launch_bounds__(256)
void gemm_kernel(const float* __restrict__ x, const float* __restrict__ Wg) {
    __shared__ float As[128][GA_LD];
    __shared__ float Bs[32][GB_LD];

    const int t    = blockIdx.y;
    const int row0 = blockIdx.x * 128;
    const int tid  = threadIdx.x;
    const int warp = tid >> 5;
    const int wr   = warp >> 2;   // 0..1  (row group of 64)
    const int wc   = warp & 3;    // 0..3  (col group of 32)

    wmma::fragment<wmma::accumulator, 16, 16, 8, float> acc[4][2];
#pragma unroll
    for (int m = 0; m < 4; m++)
#pragma unroll
        for (int n = 0; n < 2; n++) wmma::fill_fragment(acc[m][n], 0.0f);

    const float4* x4 = (const float4*)x;
    const float4* W4 = (const float4*)(Wg + (size_t)t * DIM * DIM);

    for (int k0 = 0; k0 < DIM; k0 += 32) {
        // A tile: 128 rows x 32 k  (1024 float4, 4 per thread)
#pragma unroll
        for (int i = 0; i < 4; i++) {
            int li = tid + i * 256;
            int r  = li >> 3;        // row in tile
            int c4 = li & 7;         // float4 within the 32-k chunk
            int gr = row0 + r;
            float4 v = (gr < N_NODES)
                ? __ldg(&x4[(size_t)gr * (DIM / 4) + (k0 >> 2) + c4])
                : make_float4(0.f, 0.f, 0.f, 0.f);
            As[r][c4 * 4 + 0] = wmma::__float_to_tf32(v.x);
            As[r][c4 * 4 + 1] = wmma::__float_to_tf32(v.y);
            As[r][c4 * 4 + 2] = wmma::__float_to_tf32(v.z);
            As[r][c4 * 4 + 3] = wmma::__float_to_tf32(v.w);
        }
        // B tile: 32 k x 128 cols (1024 float4, 4 per thread)
#pragma unroll
        for (int i = 0; i < 4; i++) {
            int li = tid + i * 256;
            int r  = li >> 5;        // k row
            int c4 = li & 31;        // float4 column
            float4 v = __ldg(&W4[(size_t)(k0 + r) * (DIM / 4) + c4]);
            Bs[r][c4 * 4 + 0] = wmma::__float_to_tf32(v.x);
            Bs[r][c4 * 4 + 1] = wmma::__float_to_tf32(v.y);
            Bs[r][c4 * 4 + 2] = wmma::__float_to_tf32(v.z);
            Bs[r][c4 * 4 + 3] = wmma::__float_to_tf32(v.w);
        }
        __syncthreads();

#pragma unroll
        for (int kk = 0; kk < 32; kk += 8) {
            wmma::fragment<wmma::matrix_a, 16, 16, 8, wmma::precision::tf32,
                           wmma::row_major> af[4];
            wmma::fragment<wmma::matrix_b, 16, 16, 8, wmma::precision::tf32,
                           wmma::row_major> bf[2];
#pragma unroll
            for (int m = 0; m < 4; m++)
                wmma::load_matrix_sync(af[m], &As[wr * 64 + m * 16][kk], GA_LD);
#pragma unroll
            for (int n = 0; n < 2; n++)
                wmma::load_matrix_sync(bf[n], &Bs[kk][wc * 32 + n * 16], GB_LD);
#pragma unroll
            for (int m = 0; m < 4; m++)
#pragma unroll
                for (int n = 0; n < 2; n++)
                    wmma::mma_sync(acc[m][n], af[m], bf[n], acc[m][n]);
        }
        __syncthreads();
    }

    // Store (rows padded to N_PAD -> no guard needed)
    float* yt = g_y + ((size_t)t * N_PAD + row0) * DIM;
#pragma unroll
    for (int m = 0; m < 4; m++)
#pragma unroll
        for (int n = 0; n < 2; n++)
            wmma::store_matrix_sync(
                yt + (size_t)(wr * 64 + m * 16) * DIM + wc * 32 + n * 16,
                acc[m][n], DIM, wmma::mem_row_major);
}

// ---------------------------------------------------------------------------
// Kernel 5: scatter. One warp per edge; lane l covers floats [4l,4l+4).
//   out[dst,:] += y[t,src,:] * inv[t,dst]     (vector atomic reduction)
// out (51 MB) is fully L2-resident -> atomics at LTS rate.
// ---------------------------------------------------------------------------
__global__ void scatter_kernel(const int* __restrict__ ei,
                               float* __restrict__ out) {
    long long wid = ((long long)blockIdx.x * blockDim.x + threadIdx.x) >> 5;
    int lane = threadIdx.x & 31;
    if (wid >= (long long)N_TYPES * E_PER_TYPE) return;
    int t = (int)(wid / E_PER_TYPE);
    int e = (int)(wid - (long long)t * E_PER_TYPE);

    const int* base = ei + (size_t)t * 2 * E_PER_TYPE;
    int src = __ldg(&base[e]);
    int dst = __ldg(&base[E_PER_TYPE + e]);
    if ((unsigned)src >= (unsigned)N_NODES ||
        (unsigned)dst >= (unsigned)N_NODES) return;

    float s = __ldg(&g_inv[t * N_NODES + dst]);
    float4 v = __ldg((const float4*)(g_y + ((size_t)t * N_PAD + src) * DIM) + lane);
    v.x *= s; v.y *= s; v.z *= s; v.w *= s;

    float* p = out + (size_t)dst * DIM + lane * 4;
    asm volatile("red.global.add.v4.f32 [%0], {%1, %2, %3, %4};"
                 :: "l"(p), "f"(v.x), "f"(v.y), "f"(v.z), "f"(v.w)
                 : "memory");
}

// ---------------------------------------------------------------------------
// Inputs (metadata order): x [100000,128] f32, edge_index [7,2,250000] int32,
//                          W [7,128,128] f32, b [7,128] f32.
// Output: [100000,128] f32.
// ---------------------------------------------------------------------------
extern "C" void kernel_launch(void* const* d_in, const int* in_sizes, int n_in,
                              void* d_out, int out_size) {
    (void)in_sizes; (void)n_in; (void)out_size;
    const float* x   = (const float*)d_in[0];
    const int*   ei  = (const int*)d_in[1];
    const float* W   = (const float*)d_in[2];
    const float* b   = (const float*)d_in[3];
    float*       out = (float*)d_out;

    zero_cnt_kernel<<<1024, 256>>>();

    int nedges = N_TYPES * E_PER_TYPE;
    cnt_kernel<<<(nedges + 255) / 256, 256>>>(ei);

    int ninit = N_NODES * (DIM / 4);
    init_out_kernel<<<(ninit + 255) / 256, 256>>>(b, (float4*)out);

    dim3 ggrid((N_PAD / 128), N_TYPES);
    gemm_kernel<<<ggrid, 256>>>(x, W);

    long long sthreads = (long long)nedges * 32;
    scatter_kernel<<<(int)((sthreads + 255) / 256), 256>>>(ei, out);
}